// round 1
// baseline (speedup 1.0000x reference)
#include <cuda_runtime.h>
#include <cuda_bf16.h>

#define BATCH      524288
#define N_QUBITS   16
#define NUM_CLS    10
#define TPB        256

// Output[b, s] = tail_s / sum_{s'<10} tail_s'  where tail depends only on
// qubits 12..15 (states 0..9 have zero bits for qubits 0..11, and the common
// prod_{i<12} p0_i factor cancels in the normalization).
__global__ __launch_bounds__(TPB) void qllp_kernel(
    const float* __restrict__ x,       // [BATCH, 16]
    const float* __restrict__ params,  // [16]
    float*       __restrict__ out)     // [BATCH, 10]
{
    __shared__ float s_out[TPB * NUM_CLS];   // 10 KB

    const int row = blockIdx.x * TPB + threadIdx.x;

    // Aligned 16B load of x[row, 12..15] (byte offset row*64 + 48).
    const float4 v = *reinterpret_cast<const float4*>(x + (size_t)row * N_QUBITS + 12);

    const float pr12 = __ldg(&params[12]);
    const float pr13 = __ldg(&params[13]);
    const float pr14 = __ldg(&params[14]);
    const float pr15 = __ldg(&params[15]);

    const float PI = 3.14159265358979323846f;
    const float h0 = (PI * v.x + pr12) * 0.5f;  // qubit 12
    const float h1 = (PI * v.y + pr13) * 0.5f;  // qubit 13
    const float h2 = (PI * v.z + pr14) * 0.5f;  // qubit 14
    const float h3 = (PI * v.w + pr15) * 0.5f;  // qubit 15

    float sn, cs;
    sincosf(h0, &sn, &cs); const float a0 = cs * cs, b0 = sn * sn; // p0,p1 qubit12
    sincosf(h1, &sn, &cs); const float a1 = cs * cs, b1 = sn * sn; // qubit13
    sincosf(h2, &sn, &cs); const float a2 = cs * cs, b2 = sn * sn; // qubit14
    sincosf(h3, &sn, &cs); const float a3 = cs * cs, b3 = sn * sn; // qubit15

    // bits[s, i] = (s >> (15 - i)) & 1  →  qubit12 uses bit3, ..., qubit15 uses bit0.
    // g[j] (j = 3-bit index over qubits 13,14,15):
    const float m00 = a1 * a2, m01 = a1 * b2, m10 = b1 * a2, m11 = b1 * b2;
    const float g0 = m00 * a3, g1 = m00 * b3, g2 = m01 * a3, g3 = m01 * b3;
    const float g4 = m10 * a3, g5 = m10 * b3, g6 = m11 * a3, g7 = m11 * b3;

    float t[NUM_CLS];
    t[0] = a0 * g0;  t[1] = a0 * g1;  t[2] = a0 * g2;  t[3] = a0 * g3;
    t[4] = a0 * g4;  t[5] = a0 * g5;  t[6] = a0 * g6;  t[7] = a0 * g7;
    t[8] = b0 * g0;  t[9] = b0 * g1;

    float sum = t[0];
    #pragma unroll
    for (int s = 1; s < NUM_CLS; s++) sum += t[s];
    const float inv = 1.0f / sum;

    #pragma unroll
    for (int s = 0; s < NUM_CLS; s++)
        s_out[threadIdx.x * NUM_CLS + s] = t[s] * inv;

    __syncthreads();

    // Dense coalesced writeback: TPB*10 floats = 640 float4 per block.
    float4* o4 = reinterpret_cast<float4*>(out + (size_t)blockIdx.x * (TPB * NUM_CLS));
    const float4* s4 = reinterpret_cast<const float4*>(s_out);
    #pragma unroll
    for (int i = threadIdx.x; i < (TPB * NUM_CLS) / 4; i += TPB)
        o4[i] = s4[i];
}

extern "C" void kernel_launch(void* const* d_in, const int* in_sizes, int n_in,
                              void* d_out, int out_size) {
    const float* x      = (const float*)d_in[0];
    const float* params = (const float*)d_in[1];
    float*       out    = (float*)d_out;
    qllp_kernel<<<BATCH / TPB, TPB>>>(x, params, out);
}